// round 8
// baseline (speedup 1.0000x reference)
#include <cuda_runtime.h>
#include <cstdint>

#define MAXN 100000
#define MAXE 1600000
#define IND 128
#define HID 64
#define NB_SCAN 512

// ---------------- scratch ----------------------------------------------------------
__device__ int      d_is64;
__device__ int      d_deg[MAXN];
__device__ float    d_dinv[MAXN];
__device__ float    d_g[(size_t)MAXN * HID];   // h = x @ W (unscaled)
__device__ int      d_rowptr[MAXN + 1];
__device__ int      d_cursor[MAXN];
__device__ int      d_srcs[MAXE];
__device__ int      d_bsum[NB_SCAN];
__device__ int      d_boff[NB_SCAN];
__device__ unsigned d_mask[MAXN * 2];          // dropout keep bits, 64/node

// ---------------- threefry-2x32 (JAX partitionable PRNG, key=(0,42)) ---------------
__device__ __forceinline__ void tf_round(unsigned& a, unsigned& b, int r) {
    a += b; b = __funnelshift_l(b, b, r); b ^= a;
}
__device__ __forceinline__ void threefry2x32(unsigned k0, unsigned k1,
                                             unsigned& x0, unsigned& x1) {
    unsigned k2 = k0 ^ k1 ^ 0x1BD11BDAu;
    x0 += k0; x1 += k1;
    tf_round(x0, x1, 13); tf_round(x0, x1, 15); tf_round(x0, x1, 26); tf_round(x0, x1, 6);
    x0 += k1; x1 += k2 + 1u;
    tf_round(x0, x1, 17); tf_round(x0, x1, 29); tf_round(x0, x1, 16); tf_round(x0, x1, 24);
    x0 += k2; x1 += k0 + 2u;
    tf_round(x0, x1, 13); tf_round(x0, x1, 15); tf_round(x0, x1, 26); tf_round(x0, x1, 6);
    x0 += k0; x1 += k1 + 3u;
    tf_round(x0, x1, 17); tf_round(x0, x1, 29); tf_round(x0, x1, 16); tf_round(x0, x1, 24);
    x0 += k1; x1 += k2 + 4u;
    tf_round(x0, x1, 13); tf_round(x0, x1, 15); tf_round(x0, x1, 26); tf_round(x0, x1, 6);
    x0 += k2; x1 += k0 + 5u;
}
__device__ __forceinline__ bool jax_keep(unsigned f) {
    unsigned x0 = 0u, x1 = f;
    threefry2x32(0u, 42u, x0, x1);
    return ((x0 ^ x1) >> 31) == 0u;
}

// ---------------- f32x2 packed math ------------------------------------------------
__device__ __forceinline__ unsigned long long pack2(float x, float y) {
    unsigned long long r;
    asm("mov.b64 %0, {%1, %2};" : "=l"(r) : "f"(x), "f"(y));
    return r;
}
__device__ __forceinline__ void unpack2(unsigned long long v, float& x, float& y) {
    asm("mov.b64 {%0, %1}, %2;" : "=f"(x), "=f"(y) : "l"(v));
}
__device__ __forceinline__ void ffma2(unsigned long long& d, unsigned long long a,
                                      unsigned long long b) {
    asm("fma.rn.f32x2 %0, %1, %2, %0;" : "+l"(d) : "l"(a), "l"(b));
}

// ---------------- kernels ----------------------------------------------------------
// Fused: zero d_deg (all blocks) + dtype detection (block 0 only).
__global__ void k_detect_zero(const unsigned* __restrict__ p, int n) {
    int i = blockIdx.x * blockDim.x + threadIdx.x;
    if (i < n) d_deg[i] = 0;
    if (blockIdx.x == 0) {
        __shared__ int any;
        if (threadIdx.x == 0) any = 0;
        __syncthreads();
        if (threadIdx.x < 128) {
            if (p[1 + 2 * threadIdx.x] != 0u) atomicExch(&any, 1);
        }
        __syncthreads();
        if (threadIdx.x == 0) d_is64 = (any == 0) ? 1 : 0;
    }
}

// In-degree, 4 edges per thread (vector loads -> 4x MLP on the latency-bound path).
__global__ void k_degree(const int* __restrict__ p, int E) {
    int e0 = (blockIdx.x * blockDim.x + threadIdx.x) * 4;
    if (e0 >= E) return;
    int c[4];
    if (e0 + 4 <= E) {
        if (d_is64) {
            const longlong2* q = (const longlong2*)((const long long*)p + E + e0);
            longlong2 a = q[0], b = q[1];
            c[0] = (int)a.x; c[1] = (int)a.y; c[2] = (int)b.x; c[3] = (int)b.y;
        } else {
            int4 a = *(const int4*)(p + E + e0);
            c[0] = a.x; c[1] = a.y; c[2] = a.z; c[3] = a.w;
        }
#pragma unroll
        for (int j = 0; j < 4; j++) atomicAdd(&d_deg[c[j]], 1);
    } else {
        for (int e = e0; e < E; e++) {
            int cc = d_is64 ? (int)((const long long*)p)[E + e] : p[E + e];
            atomicAdd(&d_deg[cc], 1);
        }
    }
}

// Exclusive scan of d_deg -> d_rowptr (block-local) + fused dinv.
__global__ void k_scanA(int n) {
    __shared__ int s[256];
    int tid = threadIdx.x;
    int i = blockIdx.x * 256 + tid;
    int v = (i < n) ? d_deg[i] : 0;
    if (i < n) d_dinv[i] = rsqrtf((float)(v + 1));
    s[tid] = v;
    __syncthreads();
#pragma unroll
    for (int off = 1; off < 256; off <<= 1) {
        int t = (tid >= off) ? s[tid - off] : 0;
        __syncthreads();
        s[tid] += t;
        __syncthreads();
    }
    if (i < n) d_rowptr[i] = s[tid] - v;
    if (tid == 255) d_bsum[blockIdx.x] = s[255];
}

__global__ void k_scanB(int nb) {
    __shared__ int s[NB_SCAN];
    int tid = threadIdx.x;
    s[tid] = (tid < nb) ? d_bsum[tid] : 0;
    __syncthreads();
#pragma unroll
    for (int off = 1; off < NB_SCAN; off <<= 1) {
        int t = (tid >= off) ? s[tid - off] : 0;
        __syncthreads();
        s[tid] += t;
        __syncthreads();
    }
    d_boff[tid] = (tid == 0) ? 0 : s[tid - 1];
}

__global__ void k_scanC(int n, int E) {
    int i = blockIdx.x * blockDim.x + threadIdx.x;
    if (i < n) {
        int val = d_rowptr[i] + d_boff[i >> 8];
        d_rowptr[i] = val;
        d_cursor[i] = val;
    }
    if (i == 0) d_rowptr[n] = E;
}

// CSR fill, 4 edges per thread with vector loads of both columns.
__global__ void k_fill(const int* __restrict__ p, int E) {
    int e0 = (blockIdx.x * blockDim.x + threadIdx.x) * 4;
    if (e0 >= E) return;
    int r[4], c[4];
    if (e0 + 4 <= E) {
        if (d_is64) {
            const long long* q = (const long long*)p;
            longlong2 ra = *(const longlong2*)(q + e0);
            longlong2 rb = *(const longlong2*)(q + e0 + 2);
            longlong2 ca = *(const longlong2*)(q + E + e0);
            longlong2 cb = *(const longlong2*)(q + E + e0 + 2);
            r[0] = (int)ra.x; r[1] = (int)ra.y; r[2] = (int)rb.x; r[3] = (int)rb.y;
            c[0] = (int)ca.x; c[1] = (int)ca.y; c[2] = (int)cb.x; c[3] = (int)cb.y;
        } else {
            int4 ra = *(const int4*)(p + e0);
            int4 ca = *(const int4*)(p + E + e0);
            r[0] = ra.x; r[1] = ra.y; r[2] = ra.z; r[3] = ra.w;
            c[0] = ca.x; c[1] = ca.y; c[2] = ca.z; c[3] = ca.w;
        }
#pragma unroll
        for (int j = 0; j < 4; j++) {
            int pos = atomicAdd(&d_cursor[c[j]], 1);
            d_srcs[pos] = r[j];
        }
    } else {
        for (int e = e0; e < E; e++) {
            int rr, cc;
            if (d_is64) {
                const long long* q = (const long long*)p;
                rr = (int)q[e]; cc = (int)q[E + e];
            } else { rr = p[e]; cc = p[E + e]; }
            int pos = atomicAdd(&d_cursor[cc], 1);
            d_srcs[pos] = rr;
        }
    }
}

// Dropout keep-bit mask, 32 bits per warp via ballot.  Input-independent.
__global__ void k_mask(int total) {
    int t = blockIdx.x * blockDim.x + threadIdx.x;
    bool kp = (t < total) ? jax_keep((unsigned)t) : false;
    unsigned b = __ballot_sync(0xffffffffu, kp);
    if ((threadIdx.x & 31) == 0 && t < total) d_mask[t >> 5] = b;
}

// h = x @ W via packed f32x2 FMAs.
__global__ __launch_bounds__(256) void k_gemm(const float* __restrict__ x,
                                              const float* __restrict__ W,
                                              int n) {
    __shared__ float sW[IND * HID];
    for (int t = threadIdx.x; t < (IND * HID) / 4; t += 256)
        ((float4*)sW)[t] = ((const float4*)W)[t];
    __syncthreads();

    int cg   = threadIdx.x & 7;
    int rl   = threadIdx.x >> 3;
    int row0 = blockIdx.x * 128 + rl * 4;

    const float* px[4];
#pragma unroll
    for (int i = 0; i < 4; i++) {
        int r = row0 + i; if (r >= n) r = n - 1;
        px[i] = x + (size_t)r * IND;
    }

    unsigned long long acc[4][4];
#pragma unroll
    for (int i = 0; i < 4; i++)
#pragma unroll
        for (int j = 0; j < 4; j++) acc[i][j] = 0ull;

    for (int k0 = 0; k0 < IND; k0 += 4) {
        float xr[4][4];
#pragma unroll
        for (int i = 0; i < 4; i++)
            *(float4*)xr[i] = *(const float4*)(px[i] + k0);
#pragma unroll
        for (int kk = 0; kk < 4; kk++) {
            const unsigned long long* wp =
                (const unsigned long long*)(sW + (k0 + kk) * HID + cg * 8);
            unsigned long long w0 = wp[0], w1 = wp[1], w2 = wp[2], w3 = wp[3];
#pragma unroll
            for (int i = 0; i < 4; i++) {
                unsigned long long xx = pack2(xr[i][kk], xr[i][kk]);
                ffma2(acc[i][0], xx, w0);
                ffma2(acc[i][1], xx, w1);
                ffma2(acc[i][2], xx, w2);
                ffma2(acc[i][3], xx, w3);
            }
        }
    }

#pragma unroll
    for (int i = 0; i < 4; i++) {
        int r = row0 + i;
        if (r >= n) break;
        float o[8];
#pragma unroll
        for (int j = 0; j < 4; j++) unpack2(acc[i][j], o[2 * j], o[2 * j + 1]);
        float4* gp = (float4*)(d_g + (size_t)r * HID + cg * 8);
        gp[0] = make_float4(o[0], o[1], o[2], o[3]);
        gp[1] = make_float4(o[4], o[5], o[6], o[7]);
    }
}

// Two nodes per warp, float4 lanes, with software prefetch of the next batch of
// (src, dinv) so the dependent chain src->dinv->gather overlaps across batches.
__global__ __launch_bounds__(256) void k_aggr(const float* __restrict__ bc,
                                              const float* __restrict__ Wl,
                                              const float* __restrict__ bl,
                                              float* __restrict__ out, int n) {
    int warp = (blockIdx.x * blockDim.x + threadIdx.x) >> 5;
    int lane = threadIdx.x & 31;
    int l16  = lane & 15;
    int hf   = lane >> 4;
    int halfn = (n + 1) >> 1;
    if (warp >= halfn) return;

    int node = hf ? warp + halfn : warp;
    bool valid = node < n;
    if (!valid) node = warp;

    const float4* g4 = (const float4*)d_g;
    float dn = d_dinv[node];
    float4 acc = g4[(size_t)node * 16 + l16];
    acc.x *= dn; acc.y *= dn; acc.z *= dn; acc.w *= dn;

    int k   = d_rowptr[node];
    int end = d_rowptr[node + 1];

    // prefetch batch 0
    int   r[4];
    float dr[4];
#pragma unroll
    for (int j = 0; j < 4; j++) {
        int idx = k + j;
        r[j]  = (idx < end) ? d_srcs[idx] : node;
        dr[j] = d_dinv[r[j]];
    }

    while (__any_sync(0xffffffffu, k < end)) {
        // issue current batch gathers (independent LDG.128, 8 rows in flight)
        float4 v0 = g4[(size_t)r[0] * 16 + l16];
        float4 v1 = g4[(size_t)r[1] * 16 + l16];
        float4 v2 = g4[(size_t)r[2] * 16 + l16];
        float4 v3 = g4[(size_t)r[3] * 16 + l16];

        // prefetch next batch while gathers are in flight
        int kn = k + 4;
        int rn[4]; float drn[4];
#pragma unroll
        for (int j = 0; j < 4; j++) {
            int idx = kn + j;
            rn[j]  = (idx < end) ? d_srcs[idx] : node;
            drn[j] = d_dinv[rn[j]];
        }

        if (k < end) {
            acc.x = fmaf(v0.x, dr[0], acc.x); acc.y = fmaf(v0.y, dr[0], acc.y);
            acc.z = fmaf(v0.z, dr[0], acc.z); acc.w = fmaf(v0.w, dr[0], acc.w);
        }
        if (k + 1 < end) {
            acc.x = fmaf(v1.x, dr[1], acc.x); acc.y = fmaf(v1.y, dr[1], acc.y);
            acc.z = fmaf(v1.z, dr[1], acc.z); acc.w = fmaf(v1.w, dr[1], acc.w);
        }
        if (k + 2 < end) {
            acc.x = fmaf(v2.x, dr[2], acc.x); acc.y = fmaf(v2.y, dr[2], acc.y);
            acc.z = fmaf(v2.z, dr[2], acc.z); acc.w = fmaf(v2.w, dr[2], acc.w);
        }
        if (k + 3 < end) {
            acc.x = fmaf(v3.x, dr[3], acc.x); acc.y = fmaf(v3.y, dr[3], acc.y);
            acc.z = fmaf(v3.z, dr[3], acc.z); acc.w = fmaf(v3.w, dr[3], acc.w);
        }

        k = kn;
#pragma unroll
        for (int j = 0; j < 4; j++) { r[j] = rn[j]; dr[j] = drn[j]; }
    }

    // epilogue: bias + relu + precomputed dropout mask + 64->2 projection
    int c0 = 4 * l16;
    float4 bb = ((const float4*)bc)[l16];
    float a0 = fmaxf(fmaf(dn, acc.x, bb.x), 0.f);
    float a1 = fmaxf(fmaf(dn, acc.y, bb.y), 0.f);
    float a2 = fmaxf(fmaf(dn, acc.z, bb.z), 0.f);
    float a3 = fmaxf(fmaf(dn, acc.w, bb.w), 0.f);

    unsigned mw = d_mask[node * 2 + (l16 >> 3)];
    unsigned sh = (unsigned)(c0 & 31);
    a0 = ((mw >> sh) & 1u)       ? a0 * 2.f : 0.f;
    a1 = ((mw >> (sh + 1)) & 1u) ? a1 * 2.f : 0.f;
    a2 = ((mw >> (sh + 2)) & 1u) ? a2 * 2.f : 0.f;
    a3 = ((mw >> (sh + 3)) & 1u) ? a3 * 2.f : 0.f;

    float4 wA = ((const float4*)Wl)[2 * l16];
    float4 wB = ((const float4*)Wl)[2 * l16 + 1];
    float o0 = fmaf(a0, wA.x, fmaf(a1, wA.z, fmaf(a2, wB.x, a3 * wB.z)));
    float o1 = fmaf(a0, wA.y, fmaf(a1, wA.w, fmaf(a2, wB.y, a3 * wB.w)));

#pragma unroll
    for (int off = 8; off > 0; off >>= 1) {
        o0 += __shfl_xor_sync(0xffffffffu, o0, off);
        o1 += __shfl_xor_sync(0xffffffffu, o1, off);
    }
    if (l16 == 0 && valid) {
        out[(size_t)node * 2 + 0] = o0 + bl[0];
        out[(size_t)node * 2 + 1] = o1 + bl[1];
    }
}

// ---------------- launch -----------------------------------------------------------
extern "C" void kernel_launch(void* const* d_in, const int* in_sizes, int n_in,
                              void* d_out, int out_size) {
    const float* x  = (const float*)d_in[0];
    const int*   ei = (const int*)d_in[1];
    const float* Wc = (const float*)d_in[2];
    const float* bc = (const float*)d_in[3];
    const float* Wl = (const float*)d_in[4];
    const float* bl = (const float*)d_in[5];
    float* out = (float*)d_out;

    int n = in_sizes[0] / IND;   // 100000
    int E = in_sizes[1] / 2;     // 1600000
    int nb = (n + 255) / 256;    // 391 (<= NB_SCAN)

    static cudaStream_t s2 = nullptr;
    static cudaEvent_t evFork = nullptr, evJoin = nullptr;
    if (!s2) {
        cudaStreamCreateWithFlags(&s2, cudaStreamNonBlocking);
        cudaEventCreateWithFlags(&evFork, cudaEventDisableTiming);
        cudaEventCreateWithFlags(&evJoin, cudaEventDisableTiming);
    }

    // Fork: GEMM + mask depend only on inputs -> s2, overlapping the edge pipeline.
    cudaEventRecord(evFork, 0);
    cudaStreamWaitEvent(s2, evFork, 0);
    k_gemm<<<(n + 127) / 128, 256, 0, s2>>>(x, Wc, n);
    k_mask<<<(n * 64 + 255) / 256, 256, 0, s2>>>(n * 64);
    cudaEventRecord(evJoin, s2);

    // Edge pipeline on the origin stream.
    k_detect_zero<<<nb, 256>>>((const unsigned*)ei, n);
    k_degree<<<(E / 4 + 255) / 256, 256>>>(ei, E);
    k_scanA<<<nb, 256>>>(n);
    k_scanB<<<1, NB_SCAN>>>(nb);
    k_scanC<<<nb, 256>>>(n, E);
    k_fill<<<(E / 4 + 255) / 256, 256>>>(ei, E);

    // Join, then fused aggregation + epilogue.
    cudaStreamWaitEvent(0, evJoin, 0);
    int halfn = (n + 1) / 2;
    k_aggr<<<(halfn * 32 + 255) / 256, 256>>>(bc, Wl, bl, out, n);
}

// round 9
// speedup vs baseline: 1.5873x; 1.5873x over previous
#include <cuda_runtime.h>
#include <cuda_fp16.h>
#include <cstdint>

#define MAXN 100000
#define MAXE 1600000
#define IND 128
#define HID 64
#define NB_SCAN 512

// ---------------- scratch ----------------------------------------------------------
__device__ int      d_is64;
__device__ int      d_deg[MAXN];
__device__ float    d_dinv[MAXN];
__device__ __half   d_g[(size_t)MAXN * HID];   // h = x @ W (unscaled, fp16)
__device__ int      d_rowptr[MAXN + 1];
__device__ int      d_cursor[MAXN];
__device__ int      d_srcs[MAXE];
__device__ int      d_bsum[NB_SCAN];
__device__ int      d_boff[NB_SCAN];
__device__ unsigned d_mask[MAXN * 2];          // dropout keep bits, 64/node

// ---------------- threefry-2x32 (JAX partitionable PRNG, key=(0,42)) ---------------
__device__ __forceinline__ void tf_round(unsigned& a, unsigned& b, int r) {
    a += b; b = __funnelshift_l(b, b, r); b ^= a;
}
__device__ __forceinline__ void threefry2x32(unsigned k0, unsigned k1,
                                             unsigned& x0, unsigned& x1) {
    unsigned k2 = k0 ^ k1 ^ 0x1BD11BDAu;
    x0 += k0; x1 += k1;
    tf_round(x0, x1, 13); tf_round(x0, x1, 15); tf_round(x0, x1, 26); tf_round(x0, x1, 6);
    x0 += k1; x1 += k2 + 1u;
    tf_round(x0, x1, 17); tf_round(x0, x1, 29); tf_round(x0, x1, 16); tf_round(x0, x1, 24);
    x0 += k2; x1 += k0 + 2u;
    tf_round(x0, x1, 13); tf_round(x0, x1, 15); tf_round(x0, x1, 26); tf_round(x0, x1, 6);
    x0 += k0; x1 += k1 + 3u;
    tf_round(x0, x1, 17); tf_round(x0, x1, 29); tf_round(x0, x1, 16); tf_round(x0, x1, 24);
    x0 += k1; x1 += k2 + 4u;
    tf_round(x0, x1, 13); tf_round(x0, x1, 15); tf_round(x0, x1, 26); tf_round(x0, x1, 6);
    x0 += k2; x1 += k0 + 5u;
}
__device__ __forceinline__ bool jax_keep(unsigned f) {
    unsigned x0 = 0u, x1 = f;
    threefry2x32(0u, 42u, x0, x1);
    return ((x0 ^ x1) >> 31) == 0u;
}

// ---------------- f32x2 packed math ------------------------------------------------
__device__ __forceinline__ unsigned long long pack2(float x, float y) {
    unsigned long long r;
    asm("mov.b64 %0, {%1, %2};" : "=l"(r) : "f"(x), "f"(y));
    return r;
}
__device__ __forceinline__ void unpack2(unsigned long long v, float& x, float& y) {
    asm("mov.b64 {%0, %1}, %2;" : "=f"(x), "=f"(y) : "l"(v));
}
__device__ __forceinline__ void ffma2(unsigned long long& d, unsigned long long a,
                                      unsigned long long b) {
    asm("fma.rn.f32x2 %0, %1, %2, %0;" : "+l"(d) : "l"(a), "l"(b));
}

// ---------------- kernels ----------------------------------------------------------
// Fused: zero d_deg (all blocks) + dtype detection (block 0 only).
__global__ void k_detect_zero(const unsigned* __restrict__ p, int n) {
    int i = blockIdx.x * blockDim.x + threadIdx.x;
    if (i < n) d_deg[i] = 0;
    if (blockIdx.x == 0) {
        __shared__ int any;
        if (threadIdx.x == 0) any = 0;
        __syncthreads();
        if (threadIdx.x < 128) {
            if (p[1 + 2 * threadIdx.x] != 0u) atomicExch(&any, 1);
        }
        __syncthreads();
        if (threadIdx.x == 0) d_is64 = (any == 0) ? 1 : 0;
    }
}

// In-degree of destinations (scalar form — measured best).
__global__ void k_degree(const int* __restrict__ p, int E) {
    int e = blockIdx.x * blockDim.x + threadIdx.x;
    if (e >= E) return;
    int c;
    if (d_is64) c = (int)((const long long*)p)[E + e];
    else        c = p[E + e];
    atomicAdd(&d_deg[c], 1);
}

// Exclusive scan of d_deg -> d_rowptr (block-local) + fused dinv.
__global__ void k_scanA(int n) {
    __shared__ int s[256];
    int tid = threadIdx.x;
    int i = blockIdx.x * 256 + tid;
    int v = (i < n) ? d_deg[i] : 0;
    if (i < n) d_dinv[i] = rsqrtf((float)(v + 1));
    s[tid] = v;
    __syncthreads();
#pragma unroll
    for (int off = 1; off < 256; off <<= 1) {
        int t = (tid >= off) ? s[tid - off] : 0;
        __syncthreads();
        s[tid] += t;
        __syncthreads();
    }
    if (i < n) d_rowptr[i] = s[tid] - v;
    if (tid == 255) d_bsum[blockIdx.x] = s[255];
}

__global__ void k_scanB(int nb) {
    __shared__ int s[NB_SCAN];
    int tid = threadIdx.x;
    s[tid] = (tid < nb) ? d_bsum[tid] : 0;
    __syncthreads();
#pragma unroll
    for (int off = 1; off < NB_SCAN; off <<= 1) {
        int t = (tid >= off) ? s[tid - off] : 0;
        __syncthreads();
        s[tid] += t;
        __syncthreads();
    }
    d_boff[tid] = (tid == 0) ? 0 : s[tid - 1];
}

__global__ void k_scanC(int n, int E) {
    int i = blockIdx.x * blockDim.x + threadIdx.x;
    if (i < n) {
        int val = d_rowptr[i] + d_boff[i >> 8];
        d_rowptr[i] = val;
        d_cursor[i] = val;
    }
    if (i == 0) d_rowptr[n] = E;
}

// Bucket edges by destination (scalar form — measured best).
__global__ void k_fill(const int* __restrict__ p, int E) {
    int e = blockIdx.x * blockDim.x + threadIdx.x;
    if (e >= E) return;
    int r, c;
    if (d_is64) {
        const long long* q = (const long long*)p;
        r = (int)q[e]; c = (int)q[E + e];
    } else {
        r = p[e]; c = p[E + e];
    }
    int pos = atomicAdd(&d_cursor[c], 1);
    d_srcs[pos] = r;
}

// Dropout keep-bit mask, 32 bits per warp via ballot.  Input-independent.
__global__ void k_mask(int total) {
    int t = blockIdx.x * blockDim.x + threadIdx.x;
    bool kp = (t < total) ? jax_keep((unsigned)t) : false;
    unsigned b = __ballot_sync(0xffffffffu, kp);
    if ((threadIdx.x & 31) == 0 && t < total) d_mask[t >> 5] = b;
}

// h = x @ W via packed f32x2 FMAs; store fp16 (halves gather bytes downstream).
__global__ __launch_bounds__(256) void k_gemm(const float* __restrict__ x,
                                              const float* __restrict__ W,
                                              int n) {
    __shared__ float sW[IND * HID];
    for (int t = threadIdx.x; t < (IND * HID) / 4; t += 256)
        ((float4*)sW)[t] = ((const float4*)W)[t];
    __syncthreads();

    int cg   = threadIdx.x & 7;
    int rl   = threadIdx.x >> 3;
    int row0 = blockIdx.x * 128 + rl * 4;

    const float* px[4];
#pragma unroll
    for (int i = 0; i < 4; i++) {
        int r = row0 + i; if (r >= n) r = n - 1;
        px[i] = x + (size_t)r * IND;
    }

    unsigned long long acc[4][4];
#pragma unroll
    for (int i = 0; i < 4; i++)
#pragma unroll
        for (int j = 0; j < 4; j++) acc[i][j] = 0ull;

    for (int k0 = 0; k0 < IND; k0 += 4) {
        float xr[4][4];
#pragma unroll
        for (int i = 0; i < 4; i++)
            *(float4*)xr[i] = *(const float4*)(px[i] + k0);
#pragma unroll
        for (int kk = 0; kk < 4; kk++) {
            const unsigned long long* wp =
                (const unsigned long long*)(sW + (k0 + kk) * HID + cg * 8);
            unsigned long long w0 = wp[0], w1 = wp[1], w2 = wp[2], w3 = wp[3];
#pragma unroll
            for (int i = 0; i < 4; i++) {
                unsigned long long xx = pack2(xr[i][kk], xr[i][kk]);
                ffma2(acc[i][0], xx, w0);
                ffma2(acc[i][1], xx, w1);
                ffma2(acc[i][2], xx, w2);
                ffma2(acc[i][3], xx, w3);
            }
        }
    }

#pragma unroll
    for (int i = 0; i < 4; i++) {
        int r = row0 + i;
        if (r >= n) break;
        float o[8];
#pragma unroll
        for (int j = 0; j < 4; j++) unpack2(acc[i][j], o[2 * j], o[2 * j + 1]);
        __half2 h0 = __floats2half2_rn(o[0], o[1]);
        __half2 h1 = __floats2half2_rn(o[2], o[3]);
        __half2 h2 = __floats2half2_rn(o[4], o[5]);
        __half2 h3 = __floats2half2_rn(o[6], o[7]);
        uint4 pk;
        pk.x = *(unsigned*)&h0; pk.y = *(unsigned*)&h1;
        pk.z = *(unsigned*)&h2; pk.w = *(unsigned*)&h3;
        *(uint4*)(d_g + (size_t)r * HID + cg * 8) = pk;   // 8 halves = 16 B
    }
}

// Two nodes per warp: lanes 0-15 -> node w, lanes 16-31 -> node w + ceil(n/2).
// Lane holds 4 cols as fp16 (uint2 = 8 B gather; 128 B per row per half-warp).
// Simple predicated unroll-4 body — the form ptxas schedules best (round-7 winner).
__global__ __launch_bounds__(256) void k_aggr(const float* __restrict__ bc,
                                              const float* __restrict__ Wl,
                                              const float* __restrict__ bl,
                                              float* __restrict__ out, int n) {
    int warp = (blockIdx.x * blockDim.x + threadIdx.x) >> 5;
    int lane = threadIdx.x & 31;
    int l16  = lane & 15;
    int hf   = lane >> 4;
    int halfn = (n + 1) >> 1;
    if (warp >= halfn) return;

    int node = hf ? warp + halfn : warp;
    bool valid = node < n;
    if (!valid) node = warp;

    const uint2* g2 = (const uint2*)d_g;     // 4 halves per uint2, 16 uint2 per row
    float dn = d_dinv[node];

    uint2 sraw = g2[(size_t)node * 16 + l16];
    __half2* sh = (__half2*)&sraw;
    float2 s01 = __half22float2(sh[0]);
    float2 s23 = __half22float2(sh[1]);
    float4 acc = make_float4(s01.x * dn, s01.y * dn, s23.x * dn, s23.y * dn);

    int k   = d_rowptr[node];
    int end = d_rowptr[node + 1];

    while (__any_sync(0xffffffffu, k < end)) {
#pragma unroll
        for (int j = 0; j < 4; j++) {
            int idx = k + j;
            bool p = idx < end;
            int r = p ? d_srcs[idx] : node;       // safe index when idle
            float dr = d_dinv[r];
            uint2 raw = g2[(size_t)r * 16 + l16];
            if (p) {
                __half2* hp = (__half2*)&raw;
                float2 f01 = __half22float2(hp[0]);
                float2 f23 = __half22float2(hp[1]);
                acc.x = fmaf(f01.x, dr, acc.x);
                acc.y = fmaf(f01.y, dr, acc.y);
                acc.z = fmaf(f23.x, dr, acc.z);
                acc.w = fmaf(f23.y, dr, acc.w);
            }
        }
        k += 4;
    }

    // epilogue: bias + relu + precomputed dropout mask + 64->2 projection
    int c0 = 4 * l16;
    float4 bb = ((const float4*)bc)[l16];
    float a0 = fmaxf(fmaf(dn, acc.x, bb.x), 0.f);
    float a1 = fmaxf(fmaf(dn, acc.y, bb.y), 0.f);
    float a2 = fmaxf(fmaf(dn, acc.z, bb.z), 0.f);
    float a3 = fmaxf(fmaf(dn, acc.w, bb.w), 0.f);

    unsigned mw = d_mask[node * 2 + (l16 >> 3)];
    unsigned sh2 = (unsigned)(c0 & 31);
    a0 = ((mw >> sh2) & 1u)       ? a0 * 2.f : 0.f;
    a1 = ((mw >> (sh2 + 1)) & 1u) ? a1 * 2.f : 0.f;
    a2 = ((mw >> (sh2 + 2)) & 1u) ? a2 * 2.f : 0.f;
    a3 = ((mw >> (sh2 + 3)) & 1u) ? a3 * 2.f : 0.f;

    float4 wA = ((const float4*)Wl)[2 * l16];
    float4 wB = ((const float4*)Wl)[2 * l16 + 1];
    float o0 = fmaf(a0, wA.x, fmaf(a1, wA.z, fmaf(a2, wB.x, a3 * wB.z)));
    float o1 = fmaf(a0, wA.y, fmaf(a1, wA.w, fmaf(a2, wB.y, a3 * wB.w)));

#pragma unroll
    for (int off = 8; off > 0; off >>= 1) {
        o0 += __shfl_xor_sync(0xffffffffu, o0, off);
        o1 += __shfl_xor_sync(0xffffffffu, o1, off);
    }
    if (l16 == 0 && valid) {
        out[(size_t)node * 2 + 0] = o0 + bl[0];
        out[(size_t)node * 2 + 1] = o1 + bl[1];
    }
}

// ---------------- launch -----------------------------------------------------------
extern "C" void kernel_launch(void* const* d_in, const int* in_sizes, int n_in,
                              void* d_out, int out_size) {
    const float* x  = (const float*)d_in[0];
    const int*   ei = (const int*)d_in[1];
    const float* Wc = (const float*)d_in[2];
    const float* bc = (const float*)d_in[3];
    const float* Wl = (const float*)d_in[4];
    const float* bl = (const float*)d_in[5];
    float* out = (float*)d_out;

    int n = in_sizes[0] / IND;   // 100000
    int E = in_sizes[1] / 2;     // 1600000
    int nb = (n + 255) / 256;    // 391 (<= NB_SCAN)

    static cudaStream_t s2 = nullptr;
    static cudaEvent_t evFork = nullptr, evJoin = nullptr;
    if (!s2) {
        cudaStreamCreateWithFlags(&s2, cudaStreamNonBlocking);
        cudaEventCreateWithFlags(&evFork, cudaEventDisableTiming);
        cudaEventCreateWithFlags(&evJoin, cudaEventDisableTiming);
    }

    // Fork: GEMM + mask depend only on inputs -> s2, overlapping the edge pipeline.
    cudaEventRecord(evFork, 0);
    cudaStreamWaitEvent(s2, evFork, 0);
    k_gemm<<<(n + 127) / 128, 256, 0, s2>>>(x, Wc, n);
    k_mask<<<(n * 64 + 255) / 256, 256, 0, s2>>>(n * 64);
    cudaEventRecord(evJoin, s2);

    // Edge pipeline on the origin stream.
    k_detect_zero<<<nb, 256>>>((const unsigned*)ei, n);
    k_degree<<<(E + 255) / 256, 256>>>(ei, E);
    k_scanA<<<nb, 256>>>(n);
    k_scanB<<<1, NB_SCAN>>>(nb);
    k_scanC<<<nb, 256>>>(n, E);
    k_fill<<<(E + 255) / 256, 256>>>(ei, E);

    // Join, then fused aggregation + epilogue.
    cudaStreamWaitEvent(0, evJoin, 0);
    int halfn = (n + 1) / 2;
    k_aggr<<<(halfn * 32 + 255) / 256, 256>>>(bc, Wl, bl, out, n);
}